// round 1
// baseline (speedup 1.0000x reference)
#include <cuda_runtime.h>
#include <cuda_bf16.h>
#include <math.h>

// Problem constants (from metadata: z is 8192 x 512 fp32, output scalar fp32)
#define TWO_N 8192
#define NHALF 4096           // positive index = i XOR NHALF
#define DDIM  512
#define INV_T 2.0f           // 1 / temperature (0.5)

// GEMM tiling
#define BM 128
#define BN 128
#define BK 16
#define SM_STRIDE 132        // BM + 4 pad: conflict-free transposed STS, 16B-aligned LDS.128

// Scratch (no cudaMalloc allowed)
__device__ float g_zn[TWO_N * DDIM];   // normalized z (16 MB)
__device__ float g_sumexp[TWO_N];      // per-row sum of exp(sim) excluding diagonal
__device__ float g_pos[TWO_N];         // per-row positive similarity (already * INV_T)

// ---------------------------------------------------------------------------
// Kernel 1: L2-normalize each row. One block (128 threads) per row.
// ---------------------------------------------------------------------------
__global__ void normalize_kernel(const float* __restrict__ z, float* __restrict__ zn) {
    int row = blockIdx.x;
    int t = threadIdx.x;                  // 0..127, each owns 4 consecutive floats
    const float4* src = reinterpret_cast<const float4*>(z + (size_t)row * DDIM);
    float4 v = src[t];
    float ss = v.x * v.x + v.y * v.y + v.z * v.z + v.w * v.w;

    // warp reduce
    #pragma unroll
    for (int off = 16; off > 0; off >>= 1)
        ss += __shfl_xor_sync(0xffffffffu, ss, off);

    __shared__ float wsum[4];
    if ((t & 31) == 0) wsum[t >> 5] = ss;
    __syncthreads();
    float tot = wsum[0] + wsum[1] + wsum[2] + wsum[3];

    float scale = 1.0f / fmaxf(sqrtf(tot), 1e-12f);
    float4 o;
    o.x = v.x * scale; o.y = v.y * scale; o.z = v.z * scale; o.w = v.w * scale;
    reinterpret_cast<float4*>(zn + (size_t)row * DDIM)[t] = o;
}

// ---------------------------------------------------------------------------
// Kernel 2: positive similarities (one warp per row) + zero the sumexp accum.
// ---------------------------------------------------------------------------
__global__ void pos_kernel(const float* __restrict__ zn,
                           float* __restrict__ pos, float* __restrict__ sumexp) {
    int gwarp = (blockIdx.x * blockDim.x + threadIdx.x) >> 5;
    int lane = threadIdx.x & 31;
    if (gwarp >= TWO_N) return;
    int p = gwarp ^ NHALF;

    const float4* a = reinterpret_cast<const float4*>(zn + (size_t)gwarp * DDIM);
    const float4* b = reinterpret_cast<const float4*>(zn + (size_t)p * DDIM);
    float s = 0.f;
    #pragma unroll
    for (int q = 0; q < 4; ++q) {
        int idx = q * 32 + lane;          // 128 float4 per row
        float4 va = a[idx]; float4 vb = b[idx];
        s += va.x * vb.x + va.y * vb.y + va.z * vb.z + va.w * vb.w;
    }
    #pragma unroll
    for (int off = 16; off > 0; off >>= 1)
        s += __shfl_xor_sync(0xffffffffu, s, off);
    if (lane == 0) {
        pos[gwarp] = s * INV_T;
        sumexp[gwarp] = 0.0f;             // re-zero every replay (graph-safe)
    }
}

// ---------------------------------------------------------------------------
// Kernel 3: fused GEMM + exp + row-sum.
// Each block computes one 128x128 tile of S = Zn*Zn^T over full K=512,
// applies exp(2*s) with diagonal masked, reduces per-row partials, and
// atomically adds them into g_sumexp.
// 256 threads, 8x8 micro-tile each (split 2x2 quadrants of 4x4 for
// conflict-free LDS.128), double-buffered transposed smem.
// ---------------------------------------------------------------------------
__global__ void __launch_bounds__(256, 2)
tile_kernel(const float* __restrict__ zn, float* __restrict__ sumexp) {
    const int numColTiles = TWO_N / BN;   // 64
    int rowTile = blockIdx.x / numColTiles;
    int colTile = blockIdx.x % numColTiles;
    int rowBase = rowTile * BM;
    int colBase = colTile * BN;

    __shared__ __align__(16) float As[2][BK][SM_STRIDE];
    __shared__ __align__(16) float Bs[2][BK][SM_STRIDE];

    int tid = threadIdx.x;
    int tx = tid & 15;
    int ty = tid >> 4;

    // load assignment: idx = tid*2+u ; kf = idx&3 (float4 along K) ; m = idx>>2 (row in tile)
    int kf0 = (tid * 2 + 0) & 3, m0 = (tid * 2 + 0) >> 2;
    int kf1 = (tid * 2 + 1) & 3, m1 = (tid * 2 + 1) >> 2;

    float acc[8][8];
    #pragma unroll
    for (int i = 0; i < 8; ++i)
        #pragma unroll
        for (int j = 0; j < 8; ++j) acc[i][j] = 0.f;

    float4 ra0, ra1, rb0, rb1;

    // prefetch chunk 0
    {
        int k0 = 0;
        ra0 = *reinterpret_cast<const float4*>(zn + (size_t)(rowBase + m0) * DDIM + k0 + kf0 * 4);
        ra1 = *reinterpret_cast<const float4*>(zn + (size_t)(rowBase + m1) * DDIM + k0 + kf1 * 4);
        rb0 = *reinterpret_cast<const float4*>(zn + (size_t)(colBase + m0) * DDIM + k0 + kf0 * 4);
        rb1 = *reinterpret_cast<const float4*>(zn + (size_t)(colBase + m1) * DDIM + k0 + kf1 * 4);
    }
    // store chunk 0 (transposed)
    {
        As[0][kf0 * 4 + 0][m0] = ra0.x; As[0][kf0 * 4 + 1][m0] = ra0.y;
        As[0][kf0 * 4 + 2][m0] = ra0.z; As[0][kf0 * 4 + 3][m0] = ra0.w;
        As[0][kf1 * 4 + 0][m1] = ra1.x; As[0][kf1 * 4 + 1][m1] = ra1.y;
        As[0][kf1 * 4 + 2][m1] = ra1.z; As[0][kf1 * 4 + 3][m1] = ra1.w;
        Bs[0][kf0 * 4 + 0][m0] = rb0.x; Bs[0][kf0 * 4 + 1][m0] = rb0.y;
        Bs[0][kf0 * 4 + 2][m0] = rb0.z; Bs[0][kf0 * 4 + 3][m0] = rb0.w;
        Bs[0][kf1 * 4 + 0][m1] = rb1.x; Bs[0][kf1 * 4 + 1][m1] = rb1.y;
        Bs[0][kf1 * 4 + 2][m1] = rb1.z; Bs[0][kf1 * 4 + 3][m1] = rb1.w;
    }
    __syncthreads();

    int buf = 0;
    const int NCHUNK = DDIM / BK;         // 32
    for (int t = 0; t < NCHUNK; ++t) {
        if (t + 1 < NCHUNK) {
            int k0 = (t + 1) * BK;
            ra0 = *reinterpret_cast<const float4*>(zn + (size_t)(rowBase + m0) * DDIM + k0 + kf0 * 4);
            ra1 = *reinterpret_cast<const float4*>(zn + (size_t)(rowBase + m1) * DDIM + k0 + kf1 * 4);
            rb0 = *reinterpret_cast<const float4*>(zn + (size_t)(colBase + m0) * DDIM + k0 + kf0 * 4);
            rb1 = *reinterpret_cast<const float4*>(zn + (size_t)(colBase + m1) * DDIM + k0 + kf1 * 4);
        }

        #pragma unroll
        for (int kk = 0; kk < BK; ++kk) {
            float4 a0 = *reinterpret_cast<const float4*>(&As[buf][kk][ty * 4]);
            float4 a1 = *reinterpret_cast<const float4*>(&As[buf][kk][64 + ty * 4]);
            float4 b0 = *reinterpret_cast<const float4*>(&Bs[buf][kk][tx * 4]);
            float4 b1 = *reinterpret_cast<const float4*>(&Bs[buf][kk][64 + tx * 4]);
            float a[8] = {a0.x, a0.y, a0.z, a0.w, a1.x, a1.y, a1.z, a1.w};
            float b[8] = {b0.x, b0.y, b0.z, b0.w, b1.x, b1.y, b1.z, b1.w};
            #pragma unroll
            for (int i = 0; i < 8; ++i)
                #pragma unroll
                for (int j = 0; j < 8; ++j)
                    acc[i][j] = fmaf(a[i], b[j], acc[i][j]);
        }

        if (t + 1 < NCHUNK) {
            int nb = buf ^ 1;
            As[nb][kf0 * 4 + 0][m0] = ra0.x; As[nb][kf0 * 4 + 1][m0] = ra0.y;
            As[nb][kf0 * 4 + 2][m0] = ra0.z; As[nb][kf0 * 4 + 3][m0] = ra0.w;
            As[nb][kf1 * 4 + 0][m1] = ra1.x; As[nb][kf1 * 4 + 1][m1] = ra1.y;
            As[nb][kf1 * 4 + 2][m1] = ra1.z; As[nb][kf1 * 4 + 3][m1] = ra1.w;
            Bs[nb][kf0 * 4 + 0][m0] = rb0.x; Bs[nb][kf0 * 4 + 1][m0] = rb0.y;
            Bs[nb][kf0 * 4 + 2][m0] = rb0.z; Bs[nb][kf0 * 4 + 3][m0] = rb0.w;
            Bs[nb][kf1 * 4 + 0][m1] = rb1.x; Bs[nb][kf1 * 4 + 1][m1] = rb1.y;
            Bs[nb][kf1 * 4 + 2][m1] = rb1.z; Bs[nb][kf1 * 4 + 3][m1] = rb1.w;
        }
        __syncthreads();
        buf ^= 1;
    }

    // Epilogue: exp(2*sim), mask diagonal, per-row partial sums.
    float rs[8];
    #pragma unroll
    for (int i = 0; i < 8; ++i) rs[i] = 0.f;

    #pragma unroll
    for (int i = 0; i < 8; ++i) {
        int gr = rowBase + ty * 4 + (i & 3) + ((i >> 2) << 6);
        #pragma unroll
        for (int j = 0; j < 8; ++j) {
            int gc = colBase + tx * 4 + (j & 3) + ((j >> 2) << 6);
            float e = __expf(acc[i][j] * INV_T);
            if (gr == gc) e = 0.f;        // diagonal masked
            rs[i] += e;
        }
    }

    // reduce across the 16 threads (tx) that share each row: half-warp shuffles
    #pragma unroll
    for (int i = 0; i < 8; ++i) {
        #pragma unroll
        for (int off = 8; off > 0; off >>= 1)
            rs[i] += __shfl_xor_sync(0xffffffffu, rs[i], off, 16);
    }
    if (tx == 0) {
        #pragma unroll
        for (int i = 0; i < 8; ++i) {
            int gr = rowBase + ty * 4 + (i & 3) + ((i >> 2) << 6);
            atomicAdd(&sumexp[gr], rs[i]);
        }
    }
}

// ---------------------------------------------------------------------------
// Kernel 4: loss = mean( log(sumexp_i) - pos_i )
// ---------------------------------------------------------------------------
__global__ void loss_kernel(const float* __restrict__ sumexp,
                            const float* __restrict__ pos,
                            float* __restrict__ out) {
    __shared__ float red[256];
    float s = 0.f;
    for (int i = threadIdx.x; i < TWO_N; i += 256)
        s += logf(sumexp[i]) - pos[i];
    red[threadIdx.x] = s;
    __syncthreads();
    for (int off = 128; off > 0; off >>= 1) {
        if (threadIdx.x < off) red[threadIdx.x] += red[threadIdx.x + off];
        __syncthreads();
    }
    if (threadIdx.x == 0) out[0] = red[0] / (float)TWO_N;
}

// ---------------------------------------------------------------------------
extern "C" void kernel_launch(void* const* d_in, const int* in_sizes, int n_in,
                              void* d_out, int out_size) {
    const float* z = (const float*)d_in[0];
    float* out = (float*)d_out;

    float* zn;      cudaGetSymbolAddress((void**)&zn, g_zn);
    float* sumexp;  cudaGetSymbolAddress((void**)&sumexp, g_sumexp);
    float* pos;     cudaGetSymbolAddress((void**)&pos, g_pos);

    normalize_kernel<<<TWO_N, 128>>>(z, zn);
    pos_kernel<<<(TWO_N * 32) / 256, 256>>>(zn, pos, sumexp);   // also zeroes sumexp
    tile_kernel<<<(TWO_N / BM) * (TWO_N / BN), 256>>>(zn, sumexp);
    loss_kernel<<<1, 256>>>(sumexp, pos, out);
}

// round 3
// speedup vs baseline: 9.3815x; 9.3815x over previous
#include <cuda_runtime.h>
#include <cuda_bf16.h>
#include <math.h>
#include <stdint.h>

// Problem: z (8192 x 512 fp32) -> NT-Xent loss scalar (fp32)
#define TWO_N 8192
#define NHALF 4096
#define DDIM  512
#define INV_T 2.0f

// Tiling: 128x128 CTA tiles over the symmetric sim matrix, upper triangle only.
#define TM 128
#define NT (TWO_N / TM)        // 64 tiles per side
#define NTILES (NT * (NT + 1) / 2)   // 2080
#define KC 64                  // K chunk (bf16 elems)
#define NCHUNK (DDIM / KC)     // 8
#define STRIDE 144             // smem row pitch in bytes (128B data + 16B pad)
#define TILE_BYTES (TM * STRIDE)      // 18432
#define BUF_BYTES (2 * TILE_BYTES)    // A + B per buffer
#define SMEM_BYTES (2 * BUF_BYTES)    // 73728, double buffered

// Scratch (no cudaMalloc allowed)
__device__ __nv_bfloat16 g_zb[TWO_N * DDIM];   // normalized z, bf16 (8 MB)
__device__ float g_sumexp[TWO_N];
__device__ float g_pos[TWO_N];

__device__ __forceinline__ uint32_t smem_u32(const void* p) {
    uint32_t a;
    asm("{ .reg .u64 t; cvta.to.shared.u64 t, %1; cvt.u32.u64 %0, t; }" : "=r"(a) : "l"(p));
    return a;
}

#define LDMATRIX_X4(r, addr) \
    asm volatile("ldmatrix.sync.aligned.m8n8.x4.shared.b16 {%0,%1,%2,%3}, [%4];" \
        : "=r"((r)[0]), "=r"((r)[1]), "=r"((r)[2]), "=r"((r)[3]) : "r"(addr))

#define MMA_BF16(c, a, b0, b1) \
    asm volatile("mma.sync.aligned.m16n8k16.row.col.f32.bf16.bf16.f32 " \
        "{%0,%1,%2,%3}, {%4,%5,%6,%7}, {%8,%9}, {%0,%1,%2,%3};" \
        : "+f"((c)[0]), "+f"((c)[1]), "+f"((c)[2]), "+f"((c)[3]) \
        : "r"((a)[0]), "r"((a)[1]), "r"((a)[2]), "r"((a)[3]), "r"(b0), "r"(b1))

// ---------------------------------------------------------------------------
// Kernel 1: L2-normalize each row, emit bf16. One block (128 threads) per row.
// ---------------------------------------------------------------------------
__global__ void normalize_kernel(const float* __restrict__ z, __nv_bfloat16* __restrict__ zb) {
    int row = blockIdx.x;
    int t = threadIdx.x;
    float4 v = reinterpret_cast<const float4*>(z + (size_t)row * DDIM)[t];
    float ss = v.x * v.x + v.y * v.y + v.z * v.z + v.w * v.w;
    #pragma unroll
    for (int off = 16; off > 0; off >>= 1)
        ss += __shfl_xor_sync(0xffffffffu, ss, off);
    __shared__ float wsum[4];
    if ((t & 31) == 0) wsum[t >> 5] = ss;
    __syncthreads();
    float tot = wsum[0] + wsum[1] + wsum[2] + wsum[3];
    float scale = 1.0f / fmaxf(sqrtf(tot), 1e-12f);

    __nv_bfloat162 o0 = __floats2bfloat162_rn(v.x * scale, v.y * scale);
    __nv_bfloat162 o1 = __floats2bfloat162_rn(v.z * scale, v.w * scale);
    uint2 w;
    w.x = *reinterpret_cast<uint32_t*>(&o0);
    w.y = *reinterpret_cast<uint32_t*>(&o1);
    reinterpret_cast<uint2*>(zb + (size_t)row * DDIM)[t] = w;
}

// ---------------------------------------------------------------------------
// Kernel 2: positive similarities (fp32 accum over bf16) + zero sumexp.
// ---------------------------------------------------------------------------
__global__ void pos_kernel(const __nv_bfloat16* __restrict__ zb,
                           float* __restrict__ pos, float* __restrict__ sumexp) {
    int gwarp = (blockIdx.x * blockDim.x + threadIdx.x) >> 5;
    int lane = threadIdx.x & 31;
    if (gwarp >= TWO_N) return;
    int p = gwarp ^ NHALF;

    const uint4* a = reinterpret_cast<const uint4*>(zb + (size_t)gwarp * DDIM);
    const uint4* b = reinterpret_cast<const uint4*>(zb + (size_t)p * DDIM);
    float s = 0.f;
    #pragma unroll
    for (int q = 0; q < 2; ++q) {
        uint4 va = a[q * 32 + lane];
        uint4 vb = b[q * 32 + lane];
        const uint32_t* pa = &va.x;
        const uint32_t* pb = &vb.x;
        #pragma unroll
        for (int k = 0; k < 4; ++k) {
            float2 fa = __bfloat1622float2(*reinterpret_cast<const __nv_bfloat162*>(&pa[k]));
            float2 fb = __bfloat1622float2(*reinterpret_cast<const __nv_bfloat162*>(&pb[k]));
            s += fa.x * fb.x + fa.y * fb.y;
        }
    }
    #pragma unroll
    for (int off = 16; off > 0; off >>= 1)
        s += __shfl_xor_sync(0xffffffffu, s, off);
    if (lane == 0) {
        pos[gwarp] = s * INV_T;
        sumexp[gwarp] = 0.0f;
    }
}

// ---------------------------------------------------------------------------
// Chunk loader: A tile rows [rowBase,+128), B tile rows [colBase,+128),
// K slice [koff, +64) bf16, via cp.async 16B. 2048 copies / 256 threads.
// ---------------------------------------------------------------------------
__device__ __forceinline__ void load_chunk(uint32_t sbase, uint32_t bufOff,
                                           const __nv_bfloat16* zb,
                                           int rowBase, int colBase, int koff, int tid) {
    #pragma unroll
    for (int i = 0; i < 8; ++i) {
        int item = tid + (i << 8);
        int mat = item >> 10;                 // 0 = A, 1 = B
        int idx = item & 1023;
        int r = idx >> 3, q = idx & 7;
        int grow = (mat ? colBase : rowBase) + r;
        const __nv_bfloat16* src = zb + (size_t)grow * DDIM + koff + q * 8;
        uint32_t dst = sbase + bufOff + mat * TILE_BYTES + r * STRIDE + q * 16;
        asm volatile("cp.async.cg.shared.global [%0], [%1], 16;" :: "r"(dst), "l"(src));
    }
}

// ---------------------------------------------------------------------------
// Kernel 3: bf16 HMMA tile kernel over the upper triangle, fused epilogue.
// 256 threads = 8 warps (2 x 4), warp tile 64x32, double-buffered cp.async.
// Off-diagonal tiles contribute row sums AND column sums (symmetry).
// ---------------------------------------------------------------------------
__global__ void __launch_bounds__(256, 2)
tile_kernel(const __nv_bfloat16* __restrict__ zb, float* __restrict__ sumexp) {
    extern __shared__ char smem[];
    const uint32_t sbase = smem_u32(smem);
    const int tid = threadIdx.x;
    const int lane = tid & 31;
    const int wid = tid >> 5;
    const int warpRow = wid >> 2;          // 0..1
    const int warpCol = wid & 3;           // 0..3

    // Map blockIdx.x -> upper-triangular tile (i, j), j >= i
    int t = blockIdx.x, i = 0;
    while (t >= NT - i) { t -= NT - i; ++i; }
    const int j = i + t;
    const int rowBase = i * TM;
    const int colBase = j * TM;
    const bool diag = (i == j);

    float acc[4][4][4];
    #pragma unroll
    for (int mi = 0; mi < 4; ++mi)
        #pragma unroll
        for (int ni = 0; ni < 4; ++ni)
            #pragma unroll
            for (int e = 0; e < 4; ++e) acc[mi][ni][e] = 0.f;

    // ldmatrix lane addressing: lanes 0-15 -> rows (lane&15), lanes 16-31 -> +16B (k+8)
    const uint32_t laneRow = (lane & 15) * STRIDE + ((lane >> 4) << 4);
    const uint32_t aWarp = warpRow * 64 * STRIDE + laneRow;
    const uint32_t bWarp = TILE_BYTES + warpCol * 32 * STRIDE + laneRow;

    load_chunk(sbase, 0, zb, rowBase, colBase, 0, tid);
    asm volatile("cp.async.commit_group;");

    for (int c = 0; c < NCHUNK; ++c) {
        const uint32_t bufOff = (c & 1) ? BUF_BYTES : 0;
        if (c + 1 < NCHUNK) {
            load_chunk(sbase, (c & 1) ? 0 : BUF_BYTES, zb, rowBase, colBase, (c + 1) * KC, tid);
            asm volatile("cp.async.commit_group;");
            asm volatile("cp.async.wait_group 1;");
        } else {
            asm volatile("cp.async.wait_group 0;");
        }
        __syncthreads();

        #pragma unroll
        for (int ks = 0; ks < 4; ++ks) {
            const uint32_t kb = ks * 32;    // 16 bf16 = 32B
            uint32_t ra[4][4], rb[2][4];
            #pragma unroll
            for (int mi = 0; mi < 4; ++mi)
                LDMATRIX_X4(ra[mi], sbase + bufOff + aWarp + mi * 16 * STRIDE + kb);
            #pragma unroll
            for (int nh = 0; nh < 2; ++nh)
                LDMATRIX_X4(rb[nh], sbase + bufOff + bWarp + nh * 16 * STRIDE + kb);
            #pragma unroll
            for (int mi = 0; mi < 4; ++mi)
                #pragma unroll
                for (int ni = 0; ni < 4; ++ni) {
                    const int nh = ni >> 1, sel = ni & 1;
                    MMA_BF16(acc[mi][ni], ra[mi], rb[nh][sel], rb[nh][2 + sel]);
                }
        }
        __syncthreads();
    }

    // Epilogue: exp(2*sim); row partials (mi,h) and col partials (ni,e).
    const int m0 = warpRow * 64, n0 = warpCol * 32;
    float rowp[4][2], colp[4][2];
    #pragma unroll
    for (int a = 0; a < 4; ++a) { rowp[a][0] = rowp[a][1] = 0.f; colp[a][0] = colp[a][1] = 0.f; }

    #pragma unroll
    for (int mi = 0; mi < 4; ++mi)
        #pragma unroll
        for (int ni = 0; ni < 4; ++ni)
            #pragma unroll
            for (int h = 0; h < 2; ++h)
                #pragma unroll
                for (int e = 0; e < 2; ++e) {
                    float ex = __expf(acc[mi][ni][h * 2 + e] * INV_T);
                    if (diag) {
                        int lr = m0 + mi * 16 + (lane >> 2) + 8 * h;
                        int lc = n0 + ni * 8 + (lane & 3) * 2 + e;
                        if (lr == lc) ex = 0.f;
                    }
                    rowp[mi][h] += ex;
                    colp[ni][e] += ex;
                }

    // Row partials: reduce across quad (lanes sharing t/4)
    #pragma unroll
    for (int mi = 0; mi < 4; ++mi)
        #pragma unroll
        for (int h = 0; h < 2; ++h) {
            float v = rowp[mi][h];
            v += __shfl_xor_sync(0xffffffffu, v, 1);
            v += __shfl_xor_sync(0xffffffffu, v, 2);
            rowp[mi][h] = v;
        }
    if ((lane & 3) == 0) {
        #pragma unroll
        for (int mi = 0; mi < 4; ++mi)
            #pragma unroll
            for (int h = 0; h < 2; ++h)
                atomicAdd(&sumexp[rowBase + m0 + mi * 16 + (lane >> 2) + 8 * h], rowp[mi][h]);
    }

    // Col partials (symmetric contribution): reduce across lanes sharing t%4
    if (!diag) {
        #pragma unroll
        for (int ni = 0; ni < 4; ++ni)
            #pragma unroll
            for (int e = 0; e < 2; ++e) {
                float v = colp[ni][e];
                v += __shfl_xor_sync(0xffffffffu, v, 4);
                v += __shfl_xor_sync(0xffffffffu, v, 8);
                v += __shfl_xor_sync(0xffffffffu, v, 16);
                colp[ni][e] = v;
            }
        if (lane < 4) {
            #pragma unroll
            for (int ni = 0; ni < 4; ++ni)
                #pragma unroll
                for (int e = 0; e < 2; ++e)
                    atomicAdd(&sumexp[colBase + n0 + ni * 8 + lane * 2 + e], colp[ni][e]);
        }
    }
}

// ---------------------------------------------------------------------------
// Kernel 4: loss = mean( log(sumexp_i) - pos_i )
// ---------------------------------------------------------------------------
__global__ void loss_kernel(const float* __restrict__ sumexp,
                            const float* __restrict__ pos,
                            float* __restrict__ out) {
    __shared__ float red[1024];
    float s = 0.f;
    for (int i = threadIdx.x; i < TWO_N; i += 1024)
        s += logf(sumexp[i]) - pos[i];
    red[threadIdx.x] = s;
    __syncthreads();
    for (int off = 512; off > 0; off >>= 1) {
        if (threadIdx.x < off) red[threadIdx.x] += red[threadIdx.x + off];
        __syncthreads();
    }
    if (threadIdx.x == 0) out[0] = red[0] / (float)TWO_N;
}

// ---------------------------------------------------------------------------
extern "C" void kernel_launch(void* const* d_in, const int* in_sizes, int n_in,
                              void* d_out, int out_size) {
    const float* z = (const float*)d_in[0];
    float* out = (float*)d_out;

    __nv_bfloat16* zb; cudaGetSymbolAddress((void**)&zb, g_zb);
    float* sumexp;     cudaGetSymbolAddress((void**)&sumexp, g_sumexp);
    float* pos;        cudaGetSymbolAddress((void**)&pos, g_pos);

    cudaFuncSetAttribute(tile_kernel, cudaFuncAttributeMaxDynamicSharedMemorySize, SMEM_BYTES);

    normalize_kernel<<<TWO_N, 128>>>(z, zb);
    pos_kernel<<<(TWO_N * 32) / 256, 256>>>(zb, pos, sumexp);
    tile_kernel<<<NTILES, 256, SMEM_BYTES>>>(zb, sumexp);
    loss_kernel<<<1, 1024>>>(sumexp, pos, out);
}

// round 4
// speedup vs baseline: 10.0888x; 1.0754x over previous
#include <cuda_runtime.h>
#include <cuda_bf16.h>
#include <math.h>
#include <stdint.h>

// Problem: z (8192 x 512 fp32) -> NT-Xent loss scalar (fp32)
#define TWO_N 8192
#define NHALF 4096
#define DDIM  512
#define INV_T 2.0f

// Tiling: 128x128 CTA tiles over the symmetric sim matrix, upper triangle only.
#define TM 128
#define NT (TWO_N / TM)              // 64 tiles per side
#define NTILES (NT * (NT + 1) / 2)   // 2080
#define KC 128                       // K chunk in fp8 elems (= 128B per row)
#define NCHUNK (DDIM / KC)           // 4
#define STRIDE 144                   // smem row pitch (128B data + 16B pad), conflict-free
#define TILE_BYTES (TM * STRIDE)     // 18432
#define BUF_BYTES (2 * TILE_BYTES)   // A + B per buffer
#define SMEM_BYTES (2 * BUF_BYTES)   // 73728, double buffered

// Scratch (no cudaMalloc allowed)
__device__ uint8_t g_z8[TWO_N * DDIM];   // normalized z, e4m3 (4 MB)
__device__ float g_sumexp[TWO_N];
__device__ float g_pos[TWO_N];

__device__ __forceinline__ uint32_t smem_u32(const void* p) {
    uint32_t a;
    asm("{ .reg .u64 t; cvta.to.shared.u64 t, %1; cvt.u32.u64 %0, t; }" : "=r"(a) : "l"(p));
    return a;
}

// pack two floats -> e4m3x2 (lo in low byte)
__device__ __forceinline__ uint16_t pack_e4m3x2(float lo, float hi) {
    uint16_t r;
    asm("cvt.rn.satfinite.e4m3x2.f32 %0, %1, %2;" : "=h"(r) : "f"(hi), "f"(lo));
    return r;
}

#define LDMATRIX_X4(r, addr) \
    asm volatile("ldmatrix.sync.aligned.m8n8.x4.shared.b16 {%0,%1,%2,%3}, [%4];" \
        : "=r"((r)[0]), "=r"((r)[1]), "=r"((r)[2]), "=r"((r)[3]) : "r"(addr))

#define MMA_FP8(c, a, b0, b1) \
    asm volatile("mma.sync.aligned.m16n8k32.row.col.f32.e4m3.e4m3.f32 " \
        "{%0,%1,%2,%3}, {%4,%5,%6,%7}, {%8,%9}, {%0,%1,%2,%3};" \
        : "+f"((c)[0]), "+f"((c)[1]), "+f"((c)[2]), "+f"((c)[3]) \
        : "r"((a)[0]), "r"((a)[1]), "r"((a)[2]), "r"((a)[3]), "r"(b0), "r"(b1))

// ---------------------------------------------------------------------------
// Kernel 1: L2-normalize each row, emit e4m3. One block (128 threads) per row.
// ---------------------------------------------------------------------------
__global__ void normalize_kernel(const float* __restrict__ z, uint8_t* __restrict__ z8) {
    int row = blockIdx.x;
    int t = threadIdx.x;
    float4 v = reinterpret_cast<const float4*>(z + (size_t)row * DDIM)[t];
    float ss = v.x * v.x + v.y * v.y + v.z * v.z + v.w * v.w;
    #pragma unroll
    for (int off = 16; off > 0; off >>= 1)
        ss += __shfl_xor_sync(0xffffffffu, ss, off);
    __shared__ float wsum[4];
    if ((t & 31) == 0) wsum[t >> 5] = ss;
    __syncthreads();
    float tot = wsum[0] + wsum[1] + wsum[2] + wsum[3];
    float scale = 1.0f / fmaxf(sqrtf(tot), 1e-12f);

    uint16_t w0 = pack_e4m3x2(v.x * scale, v.y * scale);
    uint16_t w1 = pack_e4m3x2(v.z * scale, v.w * scale);
    reinterpret_cast<uint32_t*>(z8 + (size_t)row * DDIM)[t] =
        (uint32_t)w0 | ((uint32_t)w1 << 16);
}

// ---------------------------------------------------------------------------
// Kernel 2: positive similarities in PURE fp32 from raw z + zero sumexp.
// One warp per row: pos_i = dot(z_i, z_p) / (|z_i||z_p|) / T.
// ---------------------------------------------------------------------------
__global__ void pos_kernel(const float* __restrict__ z,
                           float* __restrict__ pos, float* __restrict__ sumexp) {
    int gwarp = (blockIdx.x * blockDim.x + threadIdx.x) >> 5;
    int lane = threadIdx.x & 31;
    if (gwarp >= TWO_N) return;
    int p = gwarp ^ NHALF;

    const float4* a = reinterpret_cast<const float4*>(z + (size_t)gwarp * DDIM);
    const float4* b = reinterpret_cast<const float4*>(z + (size_t)p * DDIM);
    float aa = 0.f, bb = 0.f, ab = 0.f;
    #pragma unroll
    for (int q = 0; q < 4; ++q) {
        float4 va = a[q * 32 + lane];
        float4 vb = b[q * 32 + lane];
        aa += va.x * va.x + va.y * va.y + va.z * va.z + va.w * va.w;
        bb += vb.x * vb.x + vb.y * vb.y + vb.z * vb.z + vb.w * vb.w;
        ab += va.x * vb.x + va.y * vb.y + va.z * vb.z + va.w * vb.w;
    }
    #pragma unroll
    for (int off = 16; off > 0; off >>= 1) {
        aa += __shfl_xor_sync(0xffffffffu, aa, off);
        bb += __shfl_xor_sync(0xffffffffu, bb, off);
        ab += __shfl_xor_sync(0xffffffffu, ab, off);
    }
    if (lane == 0) {
        pos[gwarp] = ab * rsqrtf(aa * bb) * INV_T;
        sumexp[gwarp] = 0.0f;
    }
}

// ---------------------------------------------------------------------------
// Chunk loader: A rows [rowBase,+128), B rows [colBase,+128), K slice
// [koff, +128) fp8 bytes via cp.async 16B. 2048 copies / 256 threads.
// ---------------------------------------------------------------------------
__device__ __forceinline__ void load_chunk(uint32_t sbase, uint32_t bufOff,
                                           const uint8_t* z8,
                                           int rowBase, int colBase, int koff, int tid) {
    #pragma unroll
    for (int i = 0; i < 8; ++i) {
        int item = tid + (i << 8);
        int mat = item >> 10;                 // 0 = A, 1 = B
        int idx = item & 1023;
        int r = idx >> 3, q = idx & 7;
        int grow = (mat ? colBase : rowBase) + r;
        const uint8_t* src = z8 + (size_t)grow * DDIM + koff + q * 16;
        uint32_t dst = sbase + bufOff + mat * TILE_BYTES + r * STRIDE + q * 16;
        asm volatile("cp.async.cg.shared.global [%0], [%1], 16;" :: "r"(dst), "l"(src));
    }
}

// ---------------------------------------------------------------------------
// Kernel 3: fp8 HMMA tile kernel over the upper triangle, fused epilogue.
// 256 threads = 8 warps (2 x 4), warp tile 64x32, double-buffered cp.async.
// Off-diagonal tiles contribute row sums AND column sums (symmetry).
// ---------------------------------------------------------------------------
__global__ void __launch_bounds__(256, 2)
tile_kernel(const uint8_t* __restrict__ z8, float* __restrict__ sumexp) {
    extern __shared__ char smem[];
    const uint32_t sbase = smem_u32(smem);
    const int tid = threadIdx.x;
    const int lane = tid & 31;
    const int wid = tid >> 5;
    const int warpRow = wid >> 2;          // 0..1
    const int warpCol = wid & 3;           // 0..3

    // Map blockIdx.x -> upper-triangular tile (i, j), j >= i
    int t = blockIdx.x, i = 0;
    while (t >= NT - i) { t -= NT - i; ++i; }
    const int j = i + t;
    const int rowBase = i * TM;
    const int colBase = j * TM;
    const bool diag = (i == j);

    float acc[4][4][4];
    #pragma unroll
    for (int mi = 0; mi < 4; ++mi)
        #pragma unroll
        for (int ni = 0; ni < 4; ++ni)
            #pragma unroll
            for (int e = 0; e < 4; ++e) acc[mi][ni][e] = 0.f;

    // ldmatrix lane addressing (fp8 via b16 trick):
    // lanes 0-15 -> rows (lane&15) at +0B ; lanes 16-31 -> same rows at +16B
    // -> regs r0..r3 = exactly the e4m3 m16n8k32 A/B fragments.
    const uint32_t laneRow = (lane & 15) * STRIDE + ((lane >> 4) << 4);
    const uint32_t aWarp = warpRow * 64 * STRIDE + laneRow;
    const uint32_t bWarp = TILE_BYTES + warpCol * 32 * STRIDE + laneRow;

    load_chunk(sbase, 0, z8, rowBase, colBase, 0, tid);
    asm volatile("cp.async.commit_group;");

    for (int c = 0; c < NCHUNK; ++c) {
        const uint32_t bufOff = (c & 1) ? BUF_BYTES : 0;
        if (c + 1 < NCHUNK) {
            load_chunk(sbase, (c & 1) ? 0 : BUF_BYTES, z8, rowBase, colBase, (c + 1) * KC, tid);
            asm volatile("cp.async.commit_group;");
            asm volatile("cp.async.wait_group 1;");
        } else {
            asm volatile("cp.async.wait_group 0;");
        }
        __syncthreads();

        #pragma unroll
        for (int ks = 0; ks < 4; ++ks) {
            const uint32_t kb = ks * 32;    // 32 fp8 = 32B per k-step
            uint32_t ra[4][4], rb[2][4];
            #pragma unroll
            for (int mi = 0; mi < 4; ++mi)
                LDMATRIX_X4(ra[mi], sbase + bufOff + aWarp + mi * 16 * STRIDE + kb);
            #pragma unroll
            for (int nh = 0; nh < 2; ++nh)
                LDMATRIX_X4(rb[nh], sbase + bufOff + bWarp + nh * 16 * STRIDE + kb);
            #pragma unroll
            for (int mi = 0; mi < 4; ++mi)
                #pragma unroll
                for (int ni = 0; ni < 4; ++ni) {
                    const int nh = ni >> 1, sel = ni & 1;
                    MMA_FP8(acc[mi][ni], ra[mi], rb[nh][sel], rb[nh][2 + sel]);
                }
        }
        __syncthreads();
    }

    // Epilogue: exp(2*sim); row partials (mi,h) and col partials (ni,e).
    const int m0 = warpRow * 64, n0 = warpCol * 32;
    float rowp[4][2], colp[4][2];
    #pragma unroll
    for (int a = 0; a < 4; ++a) { rowp[a][0] = rowp[a][1] = 0.f; colp[a][0] = colp[a][1] = 0.f; }

    #pragma unroll
    for (int mi = 0; mi < 4; ++mi)
        #pragma unroll
        for (int ni = 0; ni < 4; ++ni)
            #pragma unroll
            for (int h = 0; h < 2; ++h)
                #pragma unroll
                for (int e = 0; e < 2; ++e) {
                    float ex = __expf(acc[mi][ni][h * 2 + e] * INV_T);
                    if (diag) {
                        int lr = m0 + mi * 16 + (lane >> 2) + 8 * h;
                        int lc = n0 + ni * 8 + (lane & 3) * 2 + e;
                        if (lr == lc) ex = 0.f;
                    }
                    rowp[mi][h] += ex;
                    colp[ni][e] += ex;
                }

    // Row partials: reduce across quad (lanes sharing the same row)
    #pragma unroll
    for (int mi = 0; mi < 4; ++mi)
        #pragma unroll
        for (int h = 0; h < 2; ++h) {
            float v = rowp[mi][h];
            v += __shfl_xor_sync(0xffffffffu, v, 1);
            v += __shfl_xor_sync(0xffffffffu, v, 2);
            rowp[mi][h] = v;
        }
    if ((lane & 3) == 0) {
        #pragma unroll
        for (int mi = 0; mi < 4; ++mi)
            #pragma unroll
            for (int h = 0; h < 2; ++h)
                atomicAdd(&sumexp[rowBase + m0 + mi * 16 + (lane >> 2) + 8 * h], rowp[mi][h]);
    }

    // Col partials (symmetric contribution): reduce across lanes sharing col
    if (!diag) {
        #pragma unroll
        for (int ni = 0; ni < 4; ++ni)
            #pragma unroll
            for (int e = 0; e < 2; ++e) {
                float v = colp[ni][e];
                v += __shfl_xor_sync(0xffffffffu, v, 4);
                v += __shfl_xor_sync(0xffffffffu, v, 8);
                v += __shfl_xor_sync(0xffffffffu, v, 16);
                colp[ni][e] = v;
            }
        if (lane < 4) {
            #pragma unroll
            for (int ni = 0; ni < 4; ++ni)
                #pragma unroll
                for (int e = 0; e < 2; ++e)
                    atomicAdd(&sumexp[colBase + n0 + ni * 8 + lane * 2 + e], colp[ni][e]);
        }
    }
}

// ---------------------------------------------------------------------------
// Kernel 4: loss = mean( log(sumexp_i) - pos_i )   (fast log)
// ---------------------------------------------------------------------------
__global__ void loss_kernel(const float* __restrict__ sumexp,
                            const float* __restrict__ pos,
                            float* __restrict__ out) {
    __shared__ float red[1024];
    float s = 0.f;
    #pragma unroll
    for (int q = 0; q < TWO_N / 1024; ++q) {
        int i = q * 1024 + threadIdx.x;
        s += __logf(sumexp[i]) - pos[i];
    }
    red[threadIdx.x] = s;
    __syncthreads();
    for (int off = 512; off > 0; off >>= 1) {
        if (threadIdx.x < off) red[threadIdx.x] += red[threadIdx.x + off];
        __syncthreads();
    }
    if (threadIdx.x == 0) out[0] = red[0] / (float)TWO_N;
}

// ---------------------------------------------------------------------------
extern "C" void kernel_launch(void* const* d_in, const int* in_sizes, int n_in,
                              void* d_out, int out_size) {
    const float* z = (const float*)d_in[0];
    float* out = (float*)d_out;

    uint8_t* z8;   cudaGetSymbolAddress((void**)&z8, g_z8);
    float* sumexp; cudaGetSymbolAddress((void**)&sumexp, g_sumexp);
    float* pos;    cudaGetSymbolAddress((void**)&pos, g_pos);

    cudaFuncSetAttribute(tile_kernel, cudaFuncAttributeMaxDynamicSharedMemorySize, SMEM_BYTES);

    normalize_kernel<<<TWO_N, 128>>>(z, z8);
    pos_kernel<<<(TWO_N * 32) / 256, 256>>>(z, pos, sumexp);
    tile_kernel<<<NTILES, 256, SMEM_BYTES>>>(z8, sumexp);
    loss_kernel<<<1, 1024>>>(sumexp, pos, out);
}

// round 6
// speedup vs baseline: 11.1503x; 1.1052x over previous
#include <cuda_runtime.h>
#include <math.h>
#include <stdint.h>

// Problem: z (8192 x 512 fp32) -> NT-Xent loss scalar (fp32)
#define TWO_N 8192
#define NHALF 4096
#define DDIM  512
#define INV_T 2.0f

// Tiling: 128x128 CTA tiles over the symmetric sim matrix, upper triangle only.
#define TM 128
#define NT (TWO_N / TM)              // 64
#define NTILES (NT * (NT + 1) / 2)   // 2080
#define KC 128                       // K chunk in fp8 elems (= 128B per row)
#define NCHUNK (DDIM / KC)           // 4
#define CHUNK_BYTES 16384            // 128 rows x 128 B, contiguous in g_z8 tiled layout

// SMEM: [0,16) mbarriers, stage s at 1024 + s*32768 (A 16KB + B 16KB)
#define SM_MBAR   0
#define SM_TILES  1024
#define STAGE_BYTES 32768
#define SMEM_BYTES (SM_TILES + 2 * STAGE_BYTES)   // 66560
#define CHUNK_TX   32768             // A+B bytes per stage

// Scratch (no cudaMalloc allowed).
// g_z8 layout: [tile(64)][chunk(4)][row(128)][128B], rows XOR-swizzled:
//   byte (r, cu, rem) stored at r*128 + ((cu ^ (r&7))<<4) + rem
__device__ uint8_t g_z8[TWO_N * DDIM];   // 4 MB
__device__ float g_sumexp[TWO_N];
__device__ float g_pos[TWO_N];

__device__ __forceinline__ uint32_t smem_u32(const void* p) {
    uint32_t a;
    asm("{ .reg .u64 t; cvta.to.shared.u64 t, %1; cvt.u32.u64 %0, t; }" : "=r"(a) : "l"(p));
    return a;
}
__device__ __forceinline__ uint16_t pack_e4m3x2(float lo, float hi) {
    uint16_t r;
    asm("cvt.rn.satfinite.e4m3x2.f32 %0, %1, %2;" : "=h"(r) : "f"(hi), "f"(lo));
    return r;
}
__device__ __forceinline__ void mbar_init(uint32_t m, uint32_t cnt) {
    asm volatile("mbarrier.init.shared.b64 [%0], %1;" :: "r"(m), "r"(cnt) : "memory");
}
__device__ __forceinline__ void mbar_expect_tx(uint32_t m, uint32_t bytes) {
    asm volatile("mbarrier.arrive.expect_tx.shared.b64 _, [%0], %1;" :: "r"(m), "r"(bytes) : "memory");
}
__device__ __forceinline__ void mbar_wait(uint32_t m, uint32_t parity) {
    uint32_t done;
    asm volatile(
        "{\n\t.reg .pred p;\n\t"
        "mbarrier.try_wait.parity.acquire.cta.shared::cta.b64 p, [%1], %2;\n\t"
        "selp.b32 %0, 1, 0, p;\n\t}"
        : "=r"(done) : "r"(m), "r"(parity) : "memory");
    while (!done) {
        asm volatile(
            "{\n\t.reg .pred p;\n\t"
            "mbarrier.try_wait.parity.acquire.cta.shared::cta.b64 p, [%1], %2, 0x989680;\n\t"
            "selp.b32 %0, 1, 0, p;\n\t}"
            : "=r"(done) : "r"(m), "r"(parity) : "memory");
    }
}
// Bulk async copy gmem -> smem, completion via mbarrier tx bytes.
#define BULK_G2S(dst, src, size, mbar) \
    asm volatile("cp.async.bulk.shared::cluster.global.mbarrier::complete_tx::bytes " \
                 "[%0], [%1], %2, [%3];" \
                 :: "r"(dst), "l"(src), "r"(size), "r"(mbar) : "memory")

#define LDMATRIX_X4(r, addr) \
    asm volatile("ldmatrix.sync.aligned.m8n8.x4.shared.b16 {%0,%1,%2,%3}, [%4];" \
        : "=r"((r)[0]), "=r"((r)[1]), "=r"((r)[2]), "=r"((r)[3]) : "r"(addr))

#define MMA_FP8(c, a, b0, b1) \
    asm volatile("mma.sync.aligned.m16n8k32.row.col.f32.e4m3.e4m3.f32 " \
        "{%0,%1,%2,%3}, {%4,%5,%6,%7}, {%8,%9}, {%0,%1,%2,%3};" \
        : "+f"((c)[0]), "+f"((c)[1]), "+f"((c)[2]), "+f"((c)[3]) \
        : "r"((a)[0]), "r"((a)[1]), "r"((a)[2]), "r"((a)[3]), "r"(b0), "r"(b1))

// ---------------------------------------------------------------------------
// Kernel 1: L2-normalize each row, emit e4m3 into the tiled+swizzled layout.
// One block (128 threads) per row; thread t owns bytes [4t, 4t+4).
// ---------------------------------------------------------------------------
__global__ void normalize_kernel(const float* __restrict__ z, uint8_t* __restrict__ z8) {
    int row = blockIdx.x;
    int t = threadIdx.x;
    float4 v = reinterpret_cast<const float4*>(z + (size_t)row * DDIM)[t];
    float ss = v.x * v.x + v.y * v.y + v.z * v.z + v.w * v.w;
    #pragma unroll
    for (int off = 16; off > 0; off >>= 1)
        ss += __shfl_xor_sync(0xffffffffu, ss, off);
    __shared__ float wsum[4];
    if ((t & 31) == 0) wsum[t >> 5] = ss;
    __syncthreads();
    float tot = wsum[0] + wsum[1] + wsum[2] + wsum[3];
    float scale = 1.0f / fmaxf(sqrtf(tot), 1e-12f);

    uint16_t w0 = pack_e4m3x2(v.x * scale, v.y * scale);
    uint16_t w1 = pack_e4m3x2(v.z * scale, v.w * scale);
    uint32_t word = (uint32_t)w0 | ((uint32_t)w1 << 16);

    // Tiled + swizzled destination
    int tileIdx = row >> 7, r = row & 127;
    int b = t * 4;                       // byte offset within the logical row
    int chunk = b >> 7;
    int off = b & 127;
    int cu = off >> 4, rem = off & 15;
    size_t base = ((size_t)(tileIdx * NCHUNK + chunk) * 128 + r) * 128;
    *reinterpret_cast<uint32_t*>(z8 + base + (((cu ^ (r & 7)) << 4) + rem)) = word;
}

// ---------------------------------------------------------------------------
// Kernel 2: positive similarities in pure fp32 + zero sumexp + zero out.
// ---------------------------------------------------------------------------
__global__ void pos_kernel(const float* __restrict__ z,
                           float* __restrict__ pos, float* __restrict__ sumexp,
                           float* __restrict__ out) {
    int gwarp = (blockIdx.x * blockDim.x + threadIdx.x) >> 5;
    int lane = threadIdx.x & 31;
    if (gwarp >= TWO_N) return;
    int p = gwarp ^ NHALF;

    const float4* a = reinterpret_cast<const float4*>(z + (size_t)gwarp * DDIM);
    const float4* b = reinterpret_cast<const float4*>(z + (size_t)p * DDIM);
    float aa = 0.f, bb = 0.f, ab = 0.f;
    #pragma unroll
    for (int q = 0; q < 4; ++q) {
        float4 va = a[q * 32 + lane];
        float4 vb = b[q * 32 + lane];
        aa += va.x * va.x + va.y * va.y + va.z * va.z + va.w * va.w;
        bb += vb.x * vb.x + vb.y * vb.y + vb.z * vb.z + vb.w * vb.w;
        ab += va.x * vb.x + va.y * vb.y + va.z * vb.z + va.w * vb.w;
    }
    #pragma unroll
    for (int off = 16; off > 0; off >>= 1) {
        aa += __shfl_xor_sync(0xffffffffu, aa, off);
        bb += __shfl_xor_sync(0xffffffffu, bb, off);
        ab += __shfl_xor_sync(0xffffffffu, ab, off);
    }
    if (lane == 0) {
        pos[gwarp] = ab * rsqrtf(aa * bb) * INV_T;
        sumexp[gwarp] = 0.0f;
        if (gwarp == 0) out[0] = 0.0f;
    }
}

// ---------------------------------------------------------------------------
// Kernel 3: fp8 MMA tile kernel, bulk-copy-fed, XOR-swizzled, fused epilogue.
// 256 threads = 8 warps (2 x 4), warp tile 64x32, 2-stage pipeline.
// ---------------------------------------------------------------------------
__global__ void __launch_bounds__(256, 2)
tile_kernel(const uint8_t* __restrict__ z8, float* __restrict__ sumexp) {
    extern __shared__ char smem[];
    const uint32_t sbase = smem_u32(smem);
    const int tid = threadIdx.x;
    const int lane = tid & 31;
    const int wid = tid >> 5;
    const int warpRow = wid >> 2;          // 0..1
    const int warpCol = wid & 3;           // 0..3

    // Map blockIdx.x -> upper-triangular tile (i, j), j >= i
    int t = blockIdx.x, i = 0;
    while (t >= NT - i) { t -= NT - i; ++i; }
    const int j = i + t;
    const bool diag = (i == j);
    const uint8_t* aTiles = z8 + (size_t)i * NCHUNK * CHUNK_BYTES;
    const uint8_t* bTiles = z8 + (size_t)j * NCHUNK * CHUNK_BYTES;

    // Init barriers + issue stages 0 and 1 (A + B chunk each)
    if (tid == 0) {
        mbar_init(sbase + SM_MBAR, 1);
        mbar_init(sbase + SM_MBAR + 8, 1);
        asm volatile("fence.proxy.async.shared::cta;" ::: "memory");
        mbar_expect_tx(sbase + SM_MBAR, CHUNK_TX);
        BULK_G2S(sbase + SM_TILES,               aTiles, CHUNK_BYTES, sbase + SM_MBAR);
        BULK_G2S(sbase + SM_TILES + CHUNK_BYTES, bTiles, CHUNK_BYTES, sbase + SM_MBAR);
        mbar_expect_tx(sbase + SM_MBAR + 8, CHUNK_TX);
        BULK_G2S(sbase + SM_TILES + STAGE_BYTES,               aTiles + CHUNK_BYTES, CHUNK_BYTES, sbase + SM_MBAR + 8);
        BULK_G2S(sbase + SM_TILES + STAGE_BYTES + CHUNK_BYTES, bTiles + CHUNK_BYTES, CHUNK_BYTES, sbase + SM_MBAR + 8);
    }
    __syncthreads();

    float acc[4][4][4];
    #pragma unroll
    for (int mi = 0; mi < 4; ++mi)
        #pragma unroll
        for (int ni = 0; ni < 4; ++ni)
            #pragma unroll
            for (int e = 0; e < 4; ++e) acc[mi][ni][e] = 0.f;

    // Fragment addressing: row r, 16B-unit col cu -> r*128 + ((cu ^ (r&7))<<4)
    const int lane15 = lane & 15;
    const int hi = lane >> 4;              // upper lanes take the +16B half
    uint32_t aRow[4], aSw[4], bRow[2], bSw[2];
    #pragma unroll
    for (int mi = 0; mi < 4; ++mi) {
        int r = warpRow * 64 + mi * 16 + lane15;
        aRow[mi] = r << 7; aSw[mi] = r & 7;
    }
    #pragma unroll
    for (int nh = 0; nh < 2; ++nh) {
        int r = warpCol * 32 + nh * 16 + lane15;
        bRow[nh] = r << 7; bSw[nh] = r & 7;
    }

    int ph0 = 0, ph1 = 0;
    for (int c = 0; c < NCHUNK; ++c) {
        const int buf = c & 1;
        const uint32_t mb = sbase + SM_MBAR + buf * 8;
        if (buf == 0) { mbar_wait(mb, ph0); ph0 ^= 1; }
        else          { mbar_wait(mb, ph1); ph1 ^= 1; }

        const uint32_t abase = sbase + SM_TILES + buf * STAGE_BYTES;
        const uint32_t bbase = abase + CHUNK_BYTES;

        #pragma unroll
        for (int ks = 0; ks < 4; ++ks) {
            const uint32_t cu = 2 * ks + hi;
            uint32_t ra[4][4], rb[2][4];
            #pragma unroll
            for (int mi = 0; mi < 4; ++mi)
                LDMATRIX_X4(ra[mi], abase + aRow[mi] + (((cu ^ aSw[mi])) << 4));
            #pragma unroll
            for (int nh = 0; nh < 2; ++nh)
                LDMATRIX_X4(rb[nh], bbase + bRow[nh] + (((cu ^ bSw[nh])) << 4));
            #pragma unroll
            for (int mi = 0; mi < 4; ++mi)
                #pragma unroll
                for (int ni = 0; ni < 4; ++ni) {
                    const int nh = ni >> 1, sel = ni & 1;
                    MMA_FP8(acc[mi][ni], ra[mi], rb[nh][sel], rb[nh][2 + sel]);
                }
        }
        __syncthreads();
        if (c + 2 < NCHUNK && tid == 0) {
            mbar_expect_tx(mb, CHUNK_TX);
            BULK_G2S(abase, aTiles + (c + 2) * CHUNK_BYTES, CHUNK_BYTES, mb);
            BULK_G2S(bbase, bTiles + (c + 2) * CHUNK_BYTES, CHUNK_BYTES, mb);
        }
    }

    // Epilogue: exp(2*sim); row partials (mi,h) and col partials (ni,e).
    const int m0 = warpRow * 64, n0 = warpCol * 32;
    const int rowBase = i * TM, colBase = j * TM;
    float rowp[4][2], colp[4][2];
    #pragma unroll
    for (int a = 0; a < 4; ++a) { rowp[a][0] = rowp[a][1] = 0.f; colp[a][0] = colp[a][1] = 0.f; }

    #pragma unroll
    for (int mi = 0; mi < 4; ++mi)
        #pragma unroll
        for (int ni = 0; ni < 4; ++ni)
            #pragma unroll
            for (int h = 0; h < 2; ++h)
                #pragma unroll
                for (int e = 0; e < 2; ++e) {
                    float ex = __expf(acc[mi][ni][h * 2 + e] * INV_T);
                    if (diag) {
                        int lr = m0 + mi * 16 + (lane >> 2) + 8 * h;
                        int lc = n0 + ni * 8 + (lane & 3) * 2 + e;
                        if (lr == lc) ex = 0.f;
                    }
                    rowp[mi][h] += ex;
                    colp[ni][e] += ex;
                }

    #pragma unroll
    for (int mi = 0; mi < 4; ++mi)
        #pragma unroll
        for (int h = 0; h < 2; ++h) {
            float v = rowp[mi][h];
            v += __shfl_xor_sync(0xffffffffu, v, 1);
            v += __shfl_xor_sync(0xffffffffu, v, 2);
            rowp[mi][h] = v;
        }
    if ((lane & 3) == 0) {
        #pragma unroll
        for (int mi = 0; mi < 4; ++mi)
            #pragma unroll
            for (int h = 0; h < 2; ++h)
                atomicAdd(&sumexp[rowBase + m0 + mi * 16 + (lane >> 2) + 8 * h], rowp[mi][h]);
    }

    if (!diag) {
        #pragma unroll
        for (int ni = 0; ni < 4; ++ni)
            #pragma unroll
            for (int e = 0; e < 2; ++e) {
                float v = colp[ni][e];
                v += __shfl_xor_sync(0xffffffffu, v, 4);
                v += __shfl_xor_sync(0xffffffffu, v, 8);
                v += __shfl_xor_sync(0xffffffffu, v, 16);
                colp[ni][e] = v;
            }
        if (lane < 4) {
            #pragma unroll
            for (int ni = 0; ni < 4; ++ni)
                #pragma unroll
                for (int e = 0; e < 2; ++e)
                    atomicAdd(&sumexp[colBase + n0 + ni * 8 + lane * 2 + e], colp[ni][e]);
        }
    }
}

// ---------------------------------------------------------------------------
// Kernel 4: loss partials -> atomicAdd into out (zeroed by pos_kernel).
// ---------------------------------------------------------------------------
__global__ void loss_kernel(const float* __restrict__ sumexp,
                            const float* __restrict__ pos,
                            float* __restrict__ out) {
    __shared__ float red[1024];
    int i = blockIdx.x * 1024 + threadIdx.x;
    red[threadIdx.x] = __logf(sumexp[i]) - pos[i];
    __syncthreads();
    for (int off = 512; off > 0; off >>= 1) {
        if (threadIdx.x < off) red[threadIdx.x] += red[threadIdx.x + off];
        __syncthreads();
    }
    if (threadIdx.x == 0) atomicAdd(out, red[0] * (1.0f / (float)TWO_N));
}

// ---------------------------------------------------------------------------
extern "C" void kernel_launch(void* const* d_in, const int* in_sizes, int n_in,
                              void* d_out, int out_size) {
    const float* z = (const float*)d_in[0];
    float* out = (float*)d_out;

    uint8_t* z8;   cudaGetSymbolAddress((void**)&z8, g_z8);
    float* sumexp; cudaGetSymbolAddress((void**)&sumexp, g_sumexp);
    float* pos;    cudaGetSymbolAddress((void**)&pos, g_pos);

    cudaFuncSetAttribute(tile_kernel, cudaFuncAttributeMaxDynamicSharedMemorySize, SMEM_BYTES);

    normalize_kernel<<<TWO_N, 128>>>(z, z8);
    pos_kernel<<<(TWO_N * 32) / 256, 256>>>(z, pos, sumexp, out);
    tile_kernel<<<NTILES, 256, SMEM_BYTES>>>(z8, sumexp);
    loss_kernel<<<TWO_N / 1024, 1024>>>(sumexp, pos, out);
}

// round 7
// speedup vs baseline: 11.4392x; 1.0259x over previous
#include <cuda_runtime.h>
#include <math.h>
#include <stdint.h>

// Problem: z (8192 x 512 fp32) -> NT-Xent loss scalar (fp32)
#define TWO_N 8192
#define NHALF 4096
#define DDIM  512
#define INV_T 2.0f

// Tiling: 128x128 CTA tiles over the symmetric sim matrix, upper triangle only.
#define TM 128
#define NT (TWO_N / TM)              // 64
#define NTILES (NT * (NT + 1) / 2)   // 2080
#define KC 128                       // K chunk in fp8 elems (= 128B per row)
#define NCHUNK (DDIM / KC)           // 4
#define CHUNK_BYTES 16384            // 128 rows x 128 B, contiguous in g_z8 tiled layout

// SMEM: [0,24) mbarriers (3), stage s at 1024 + s*32768 (A 16KB + B 16KB)
#define NSTAGE 3
#define SM_MBAR   0
#define SM_TILES  1024
#define STAGE_BYTES 32768
#define SMEM_BYTES (SM_TILES + NSTAGE * STAGE_BYTES)   // 99328 -> occ 2
#define CHUNK_TX   32768             // A+B bytes per stage

// Scratch (no cudaMalloc allowed).
// g_z8 layout: [tile(64)][chunk(4)][row(128)][128B], rows XOR-swizzled:
//   byte (r, cu, rem) stored at r*128 + ((cu ^ (r&7))<<4) + rem
__device__ uint8_t g_z8[TWO_N * DDIM];   // 4 MB
__device__ float g_sumexp[TWO_N];
__device__ float g_pos[TWO_N];

__device__ __forceinline__ uint32_t smem_u32(const void* p) {
    uint32_t a;
    asm("{ .reg .u64 t; cvta.to.shared.u64 t, %1; cvt.u32.u64 %0, t; }" : "=r"(a) : "l"(p));
    return a;
}
__device__ __forceinline__ uint16_t pack_e4m3x2(float lo, float hi) {
    uint16_t r;
    asm("cvt.rn.satfinite.e4m3x2.f32 %0, %1, %2;" : "=h"(r) : "f"(hi), "f"(lo));
    return r;
}
__device__ __forceinline__ void mbar_init(uint32_t m, uint32_t cnt) {
    asm volatile("mbarrier.init.shared.b64 [%0], %1;" :: "r"(m), "r"(cnt) : "memory");
}
__device__ __forceinline__ void mbar_expect_tx(uint32_t m, uint32_t bytes) {
    asm volatile("mbarrier.arrive.expect_tx.shared.b64 _, [%0], %1;" :: "r"(m), "r"(bytes) : "memory");
}
__device__ __forceinline__ void mbar_wait(uint32_t m, uint32_t parity) {
    uint32_t done;
    asm volatile(
        "{\n\t.reg .pred p;\n\t"
        "mbarrier.try_wait.parity.acquire.cta.shared::cta.b64 p, [%1], %2;\n\t"
        "selp.b32 %0, 1, 0, p;\n\t}"
        : "=r"(done) : "r"(m), "r"(parity) : "memory");
    while (!done) {
        asm volatile(
            "{\n\t.reg .pred p;\n\t"
            "mbarrier.try_wait.parity.acquire.cta.shared::cta.b64 p, [%1], %2, 0x989680;\n\t"
            "selp.b32 %0, 1, 0, p;\n\t}"
            : "=r"(done) : "r"(m), "r"(parity) : "memory");
    }
}
// Bulk async copy gmem -> smem, completion via mbarrier tx bytes.
#define BULK_G2S(dst, src, size, mbar) \
    asm volatile("cp.async.bulk.shared::cluster.global.mbarrier::complete_tx::bytes " \
                 "[%0], [%1], %2, [%3];" \
                 :: "r"(dst), "l"(src), "r"(size), "r"(mbar) : "memory")

#define LDMATRIX_X4(r, addr) \
    asm volatile("ldmatrix.sync.aligned.m8n8.x4.shared.b16 {%0,%1,%2,%3}, [%4];" \
        : "=r"((r)[0]), "=r"((r)[1]), "=r"((r)[2]), "=r"((r)[3]) : "r"(addr))

#define MMA_FP8(c, a, b0, b1) \
    asm volatile("mma.sync.aligned.m16n8k32.row.col.f32.e4m3.e4m3.f32 " \
        "{%0,%1,%2,%3}, {%4,%5,%6,%7}, {%8,%9}, {%0,%1,%2,%3};" \
        : "+f"((c)[0]), "+f"((c)[1]), "+f"((c)[2]), "+f"((c)[3]) \
        : "r"((a)[0]), "r"((a)[1]), "r"((a)[2]), "r"((a)[3]), "r"(b0), "r"(b1))

// ---------------------------------------------------------------------------
// Kernel 1: L2-normalize each row, emit e4m3 into the tiled+swizzled layout.
// ---------------------------------------------------------------------------
__global__ void normalize_kernel(const float* __restrict__ z, uint8_t* __restrict__ z8) {
    int row = blockIdx.x;
    int t = threadIdx.x;
    float4 v = reinterpret_cast<const float4*>(z + (size_t)row * DDIM)[t];
    float ss = v.x * v.x + v.y * v.y + v.z * v.z + v.w * v.w;
    #pragma unroll
    for (int off = 16; off > 0; off >>= 1)
        ss += __shfl_xor_sync(0xffffffffu, ss, off);
    __shared__ float wsum[4];
    if ((t & 31) == 0) wsum[t >> 5] = ss;
    __syncthreads();
    float tot = wsum[0] + wsum[1] + wsum[2] + wsum[3];
    float scale = 1.0f / fmaxf(sqrtf(tot), 1e-12f);

    uint16_t w0 = pack_e4m3x2(v.x * scale, v.y * scale);
    uint16_t w1 = pack_e4m3x2(v.z * scale, v.w * scale);
    uint32_t word = (uint32_t)w0 | ((uint32_t)w1 << 16);

    int tileIdx = row >> 7, r = row & 127;
    int b = t * 4;
    int chunk = b >> 7;
    int off = b & 127;
    int cu = off >> 4, rem = off & 15;
    size_t base = ((size_t)(tileIdx * NCHUNK + chunk) * 128 + r) * 128;
    *reinterpret_cast<uint32_t*>(z8 + base + (((cu ^ (r & 7)) << 4) + rem)) = word;
}

// ---------------------------------------------------------------------------
// Kernel 2: positive similarities in pure fp32 + zero sumexp + zero out.
// ---------------------------------------------------------------------------
__global__ void pos_kernel(const float* __restrict__ z,
                           float* __restrict__ pos, float* __restrict__ sumexp,
                           float* __restrict__ out) {
    int gwarp = (blockIdx.x * blockDim.x + threadIdx.x) >> 5;
    int lane = threadIdx.x & 31;
    if (gwarp >= TWO_N) return;
    int p = gwarp ^ NHALF;

    const float4* a = reinterpret_cast<const float4*>(z + (size_t)gwarp * DDIM);
    const float4* b = reinterpret_cast<const float4*>(z + (size_t)p * DDIM);
    float aa = 0.f, bb = 0.f, ab = 0.f;
    #pragma unroll
    for (int q = 0; q < 4; ++q) {
        float4 va = a[q * 32 + lane];
        float4 vb = b[q * 32 + lane];
        aa += va.x * va.x + va.y * va.y + va.z * va.z + va.w * va.w;
        bb += vb.x * vb.x + vb.y * vb.y + vb.z * vb.z + vb.w * vb.w;
        ab += va.x * vb.x + va.y * vb.y + va.z * vb.z + va.w * vb.w;
    }
    #pragma unroll
    for (int off = 16; off > 0; off >>= 1) {
        aa += __shfl_xor_sync(0xffffffffu, aa, off);
        bb += __shfl_xor_sync(0xffffffffu, bb, off);
        ab += __shfl_xor_sync(0xffffffffu, ab, off);
    }
    if (lane == 0) {
        pos[gwarp] = ab * rsqrtf(aa * bb) * INV_T;
        sumexp[gwarp] = 0.0f;
        if (gwarp == 0) out[0] = 0.0f;
    }
}

// ---------------------------------------------------------------------------
// Kernel 3: fp8 MMA tile kernel, 3-stage bulk-copy pipeline, fused epilogue.
// 256 threads = 8 warps (2 x 4), warp tile 64x32.
// ---------------------------------------------------------------------------
__global__ void __launch_bounds__(256, 2)
tile_kernel(const uint8_t* __restrict__ z8, float* __restrict__ sumexp) {
    extern __shared__ char smem[];
    const uint32_t sbase = smem_u32(smem);
    const int tid = threadIdx.x;
    const int lane = tid & 31;
    const int wid = tid >> 5;
    const int warpRow = wid >> 2;          // 0..1
    const int warpCol = wid & 3;           // 0..3

    // Map blockIdx.x -> upper-triangular tile (i, j), j >= i
    int t = blockIdx.x, i = 0;
    while (t >= NT - i) { t -= NT - i; ++i; }
    const int j = i + t;
    const bool diag = (i == j);
    const uint8_t* aTiles = z8 + (size_t)i * NCHUNK * CHUNK_BYTES;
    const uint8_t* bTiles = z8 + (size_t)j * NCHUNK * CHUNK_BYTES;

    // Init barriers + issue chunks 0..2 into stages 0..2.
    if (tid == 0) {
        #pragma unroll
        for (int s = 0; s < NSTAGE; ++s) mbar_init(sbase + SM_MBAR + 8 * s, 1);
        asm volatile("fence.proxy.async.shared::cta;" ::: "memory");
        #pragma unroll
        for (int s = 0; s < NSTAGE; ++s) {
            uint32_t mb = sbase + SM_MBAR + 8 * s;
            uint32_t dst = sbase + SM_TILES + s * STAGE_BYTES;
            mbar_expect_tx(mb, CHUNK_TX);
            BULK_G2S(dst,               aTiles + s * CHUNK_BYTES, CHUNK_BYTES, mb);
            BULK_G2S(dst + CHUNK_BYTES, bTiles + s * CHUNK_BYTES, CHUNK_BYTES, mb);
        }
    }
    __syncthreads();

    float acc[4][4][4];
    #pragma unroll
    for (int mi = 0; mi < 4; ++mi)
        #pragma unroll
        for (int ni = 0; ni < 4; ++ni)
            #pragma unroll
            for (int e = 0; e < 4; ++e) acc[mi][ni][e] = 0.f;

    // Fragment addressing: row r, 16B-unit col cu -> r*128 + ((cu ^ (r&7))<<4)
    const int lane15 = lane & 15;
    const int hi = lane >> 4;
    uint32_t aRow[4], aSw[4], bRow[2], bSw[2];
    #pragma unroll
    for (int mi = 0; mi < 4; ++mi) {
        int r = warpRow * 64 + mi * 16 + lane15;
        aRow[mi] = r << 7; aSw[mi] = r & 7;
    }
    #pragma unroll
    for (int nh = 0; nh < 2; ++nh) {
        int r = warpCol * 32 + nh * 16 + lane15;
        bRow[nh] = r << 7; bSw[nh] = r & 7;
    }

    #pragma unroll
    for (int c = 0; c < NCHUNK; ++c) {
        const int s = c % NSTAGE;
        const uint32_t mb = sbase + SM_MBAR + 8 * s;
        mbar_wait(mb, (c < NSTAGE) ? 0 : 1);

        const uint32_t abase = sbase + SM_TILES + s * STAGE_BYTES;
        const uint32_t bbase = abase + CHUNK_BYTES;

        #pragma unroll
        for (int ks = 0; ks < 4; ++ks) {
            const uint32_t cu = 2 * ks + hi;
            uint32_t ra[4][4], rb[2][4];
            #pragma unroll
            for (int mi = 0; mi < 4; ++mi)
                LDMATRIX_X4(ra[mi], abase + aRow[mi] + (((cu ^ aSw[mi])) << 4));
            #pragma unroll
            for (int nh = 0; nh < 2; ++nh)
                LDMATRIX_X4(rb[nh], bbase + bRow[nh] + (((cu ^ bSw[nh])) << 4));
            #pragma unroll
            for (int mi = 0; mi < 4; ++mi)
                #pragma unroll
                for (int ni = 0; ni < 4; ++ni) {
                    const int nh = ni >> 1, sel = ni & 1;
                    MMA_FP8(acc[mi][ni], ra[mi], rb[nh][sel], rb[nh][2 + sel]);
                }
        }

        // After all warps consumed stage s (chunk c), refill it with chunk c+NSTAGE.
        if (c + NSTAGE < NCHUNK) {
            __syncthreads();
            if (tid == 0) {
                mbar_expect_tx(mb, CHUNK_TX);
                BULK_G2S(abase, aTiles + (c + NSTAGE) * CHUNK_BYTES, CHUNK_BYTES, mb);
                BULK_G2S(bbase, bTiles + (c + NSTAGE) * CHUNK_BYTES, CHUNK_BYTES, mb);
            }
        }
    }

    // Epilogue: exp(2*sim); row partials (mi,h) and col partials (ni,e).
    const int m0 = warpRow * 64, n0 = warpCol * 32;
    const int rowBase = i * TM, colBase = j * TM;
    float rowp[4][2], colp[4][2];
    #pragma unroll
    for (int a = 0; a < 4; ++a) { rowp[a][0] = rowp[a][1] = 0.f; colp[a][0] = colp[a][1] = 0.f; }

    #pragma unroll
    for (int mi = 0; mi < 4; ++mi)
        #pragma unroll
        for (int ni = 0; ni < 4; ++ni)
            #pragma unroll
            for (int h = 0; h < 2; ++h)
                #pragma unroll
                for (int e = 0; e < 2; ++e) {
                    float ex = __expf(acc[mi][ni][h * 2 + e] * INV_T);
                    if (diag) {
                        int lr = m0 + mi * 16 + (lane >> 2) + 8 * h;
                        int lc = n0 + ni * 8 + (lane & 3) * 2 + e;
                        if (lr == lc) ex = 0.f;
                    }
                    rowp[mi][h] += ex;
                    colp[ni][e] += ex;
                }

    #pragma unroll
    for (int mi = 0; mi < 4; ++mi)
        #pragma unroll
        for (int h = 0; h < 2; ++h) {
            float v = rowp[mi][h];
            v += __shfl_xor_sync(0xffffffffu, v, 1);
            v += __shfl_xor_sync(0xffffffffu, v, 2);
            rowp[mi][h] = v;
        }
    if ((lane & 3) == 0) {
        #pragma unroll
        for (int mi = 0; mi < 4; ++mi)
            #pragma unroll
            for (int h = 0; h < 2; ++h)
                atomicAdd(&sumexp[rowBase + m0 + mi * 16 + (lane >> 2) + 8 * h], rowp[mi][h]);
    }

    if (!diag) {
        #pragma unroll
        for (int ni = 0; ni < 4; ++ni)
            #pragma unroll
            for (int e = 0; e < 2; ++e) {
                float v = colp[ni][e];
                v += __shfl_xor_sync(0xffffffffu, v, 4);
                v += __shfl_xor_sync(0xffffffffu, v, 8);
                v += __shfl_xor_sync(0xffffffffu, v, 16);
                colp[ni][e] = v;
            }
        if (lane < 4) {
            #pragma unroll
            for (int ni = 0; ni < 4; ++ni)
                #pragma unroll
                for (int e = 0; e < 2; ++e)
                    atomicAdd(&sumexp[colBase + n0 + ni * 8 + lane * 2 + e], colp[ni][e]);
        }
    }
}

// ---------------------------------------------------------------------------
// Kernel 4: loss partials -> atomicAdd into out (zeroed by pos_kernel).
// ---------------------------------------------------------------------------
__global__ void loss_kernel(const float* __restrict__ sumexp,
                            const float* __restrict__ pos,
                            float* __restrict__ out) {
    __shared__ float red[1024];
    int i = blockIdx.x * 1024 + threadIdx.x;
    red[threadIdx.x] = __logf(sumexp[i]) - pos[i];
    __syncthreads();
    for (int off = 512; off > 0; off >>= 1) {
        if (threadIdx.x < off) red[threadIdx.x] += red[threadIdx.x + off];
        __syncthreads();
    }
    if (threadIdx.x == 0) atomicAdd(out, red[0] * (1.0f / (float)TWO_N));
}

// ---------------------------------------------------------------------------
extern "C" void kernel_launch(void* const* d_in, const int* in_sizes, int n_in,
                              void* d_out, int out_size) {
    const float* z = (const float*)d_in[0];
    float* out = (float*)d_out;

    uint8_t* z8;   cudaGetSymbolAddress((void**)&z8, g_z8);
    float* sumexp; cudaGetSymbolAddress((void**)&sumexp, g_sumexp);
    float* pos;    cudaGetSymbolAddress((void**)&pos, g_pos);

    cudaFuncSetAttribute(tile_kernel, cudaFuncAttributeMaxDynamicSharedMemorySize, SMEM_BYTES);

    normalize_kernel<<<TWO_N, 128>>>(z, z8);
    pos_kernel<<<(TWO_N * 32) / 256, 256>>>(z, pos, sumexp, out);
    tile_kernel<<<NTILES, 256, SMEM_BYTES>>>(z8, sumexp);
    loss_kernel<<<TWO_N / 1024, 1024>>>(sumexp, pos, out);
}

// round 8
// speedup vs baseline: 12.1432x; 1.0615x over previous
#include <cuda_runtime.h>
#include <cuda_fp16.h>
#include <math.h>
#include <stdint.h>

// Problem: z (8192 x 512 fp32) -> NT-Xent loss scalar (fp32)
#define TWO_N 8192
#define NHALF 4096
#define DDIM  512
#define INV_T 2.0f

// Tiling: 128x128 CTA tiles over the symmetric sim matrix, upper triangle only.
#define TM 128
#define NT (TWO_N / TM)              // 64
#define NTILES (NT * (NT + 1) / 2)   // 2080
#define KC 128                       // K chunk in fp8 elems (= 128B per row)
#define NCHUNK (DDIM / KC)           // 4
#define CHUNK_BYTES 16384            // 128 rows x 128 B, contiguous in g_z8 tiled layout

// SMEM: [0,24) mbarriers (3), stage s at 1024 + s*32768 (A 16KB + B 16KB)
#define NSTAGE 3
#define SM_MBAR   0
#define SM_TILES  1024
#define STAGE_BYTES 32768
#define SMEM_BYTES (SM_TILES + NSTAGE * STAGE_BYTES)   // 99328 -> occ 2
#define CHUNK_TX   32768             // A+B bytes per stage

// Scratch (no cudaMalloc allowed).
// g_z8 layout: [tile(64)][chunk(4)][row(128)][128B], rows XOR-swizzled:
//   byte (r, cu, rem) stored at r*128 + ((cu ^ (r&7))<<4) + rem
__device__ uint8_t g_z8[TWO_N * DDIM];   // 4 MB
__device__ float g_sumexp[TWO_N];
__device__ float g_pos[TWO_N];

__device__ __forceinline__ uint32_t smem_u32(const void* p) {
    uint32_t a;
    asm("{ .reg .u64 t; cvta.to.shared.u64 t, %1; cvt.u32.u64 %0, t; }" : "=r"(a) : "l"(p));
    return a;
}
__device__ __forceinline__ uint16_t pack_e4m3x2(float lo, float hi) {
    uint16_t r;
    asm("cvt.rn.satfinite.e4m3x2.f32 %0, %1, %2;" : "=h"(r) : "f"(hi), "f"(lo));
    return r;
}
__device__ __forceinline__ void mbar_init(uint32_t m, uint32_t cnt) {
    asm volatile("mbarrier.init.shared.b64 [%0], %1;" :: "r"(m), "r"(cnt) : "memory");
}
__device__ __forceinline__ void mbar_expect_tx(uint32_t m, uint32_t bytes) {
    asm volatile("mbarrier.arrive.expect_tx.shared.b64 _, [%0], %1;" :: "r"(m), "r"(bytes) : "memory");
}
__device__ __forceinline__ void mbar_wait(uint32_t m, uint32_t parity) {
    uint32_t done;
    asm volatile(
        "{\n\t.reg .pred p;\n\t"
        "mbarrier.try_wait.parity.acquire.cta.shared::cta.b64 p, [%1], %2;\n\t"
        "selp.b32 %0, 1, 0, p;\n\t}"
        : "=r"(done) : "r"(m), "r"(parity) : "memory");
    while (!done) {
        asm volatile(
            "{\n\t.reg .pred p;\n\t"
            "mbarrier.try_wait.parity.acquire.cta.shared::cta.b64 p, [%1], %2, 0x989680;\n\t"
            "selp.b32 %0, 1, 0, p;\n\t}"
            : "=r"(done) : "r"(m), "r"(parity) : "memory");
    }
}
// Bulk async copy gmem -> smem, completion via mbarrier tx bytes.
#define BULK_G2S(dst, src, size, mbar) \
    asm volatile("cp.async.bulk.shared::cluster.global.mbarrier::complete_tx::bytes " \
                 "[%0], [%1], %2, [%3];" \
                 :: "r"(dst), "l"(src), "r"(size), "r"(mbar) : "memory")

#define LDMATRIX_X4(r, addr) \
    asm volatile("ldmatrix.sync.aligned.m8n8.x4.shared.b16 {%0,%1,%2,%3}, [%4];" \
        : "=r"((r)[0]), "=r"((r)[1]), "=r"((r)[2]), "=r"((r)[3]) : "r"(addr))

// fp8 MMA with f16 accumulators: D/C are 2 regs (4 halves).
#define MMA_FP8_F16(c, a, b0, b1) \
    asm volatile("mma.sync.aligned.m16n8k32.row.col.f16.e4m3.e4m3.f16 " \
        "{%0,%1}, {%2,%3,%4,%5}, {%6,%7}, {%0,%1};" \
        : "+r"((c)[0]), "+r"((c)[1]) \
        : "r"((a)[0]), "r"((a)[1]), "r"((a)[2]), "r"((a)[3]), "r"(b0), "r"(b1))

// ---------------------------------------------------------------------------
// Kernel 1: L2-normalize each row, emit e4m3 into the tiled+swizzled layout.
// ---------------------------------------------------------------------------
__global__ void normalize_kernel(const float* __restrict__ z, uint8_t* __restrict__ z8) {
    int row = blockIdx.x;
    int t = threadIdx.x;
    float4 v = reinterpret_cast<const float4*>(z + (size_t)row * DDIM)[t];
    float ss = v.x * v.x + v.y * v.y + v.z * v.z + v.w * v.w;
    #pragma unroll
    for (int off = 16; off > 0; off >>= 1)
        ss += __shfl_xor_sync(0xffffffffu, ss, off);
    __shared__ float wsum[4];
    if ((t & 31) == 0) wsum[t >> 5] = ss;
    __syncthreads();
    float tot = wsum[0] + wsum[1] + wsum[2] + wsum[3];
    float scale = 1.0f / fmaxf(sqrtf(tot), 1e-12f);

    uint16_t w0 = pack_e4m3x2(v.x * scale, v.y * scale);
    uint16_t w1 = pack_e4m3x2(v.z * scale, v.w * scale);
    uint32_t word = (uint32_t)w0 | ((uint32_t)w1 << 16);

    int tileIdx = row >> 7, r = row & 127;
    int b = t * 4;
    int chunk = b >> 7;
    int off = b & 127;
    int cu = off >> 4, rem = off & 15;
    size_t base = ((size_t)(tileIdx * NCHUNK + chunk) * 128 + r) * 128;
    *reinterpret_cast<uint32_t*>(z8 + base + (((cu ^ (r & 7)) << 4) + rem)) = word;
}

// ---------------------------------------------------------------------------
// Kernel 2: positive similarities in pure fp32 + zero sumexp + zero out.
// ---------------------------------------------------------------------------
__global__ void pos_kernel(const float* __restrict__ z,
                           float* __restrict__ pos, float* __restrict__ sumexp,
                           float* __restrict__ out) {
    int gwarp = (blockIdx.x * blockDim.x + threadIdx.x) >> 5;
    int lane = threadIdx.x & 31;
    if (gwarp >= TWO_N) return;
    int p = gwarp ^ NHALF;

    const float4* a = reinterpret_cast<const float4*>(z + (size_t)gwarp * DDIM);
    const float4* b = reinterpret_cast<const float4*>(z + (size_t)p * DDIM);
    float aa = 0.f, bb = 0.f, ab = 0.f;
    #pragma unroll
    for (int q = 0; q < 4; ++q) {
        float4 va = a[q * 32 + lane];
        float4 vb = b[q * 32 + lane];
        aa += va.x * va.x + va.y * va.y + va.z * va.z + va.w * va.w;
        bb += vb.x * vb.x + vb.y * vb.y + vb.z * vb.z + vb.w * vb.w;
        ab += va.x * vb.x + va.y * vb.y + va.z * vb.z + va.w * vb.w;
    }
    #pragma unroll
    for (int off = 16; off > 0; off >>= 1) {
        aa += __shfl_xor_sync(0xffffffffu, aa, off);
        bb += __shfl_xor_sync(0xffffffffu, bb, off);
        ab += __shfl_xor_sync(0xffffffffu, ab, off);
    }
    if (lane == 0) {
        pos[gwarp] = ab * rsqrtf(aa * bb) * INV_T;
        sumexp[gwarp] = 0.0f;
        if (gwarp == 0) out[0] = 0.0f;
    }
}

// ---------------------------------------------------------------------------
// Kernel 3: fp8 MMA (f16 accum) tile kernel, 3-stage bulk pipeline, fused
// epilogue. 256 threads = 8 warps (2 x 4), warp tile 64x32.
// ---------------------------------------------------------------------------
__global__ void __launch_bounds__(256, 2)
tile_kernel(const uint8_t* __restrict__ z8, float* __restrict__ sumexp) {
    extern __shared__ char smem[];
    const uint32_t sbase = smem_u32(smem);
    const int tid = threadIdx.x;
    const int lane = tid & 31;
    const int wid = tid >> 5;
    const int warpRow = wid >> 2;          // 0..1
    const int warpCol = wid & 3;           // 0..3

    // Map blockIdx.x -> upper-triangular tile (i, j), j >= i
    int t = blockIdx.x, i = 0;
    while (t >= NT - i) { t -= NT - i; ++i; }
    const int j = i + t;
    const bool diag = (i == j);
    const uint8_t* aTiles = z8 + (size_t)i * NCHUNK * CHUNK_BYTES;
    const uint8_t* bTiles = z8 + (size_t)j * NCHUNK * CHUNK_BYTES;

    // Init barriers + issue chunks 0..2 into stages 0..2.
    if (tid == 0) {
        #pragma unroll
        for (int s = 0; s < NSTAGE; ++s) mbar_init(sbase + SM_MBAR + 8 * s, 1);
        asm volatile("fence.proxy.async.shared::cta;" ::: "memory");
        #pragma unroll
        for (int s = 0; s < NSTAGE; ++s) {
            uint32_t mb = sbase + SM_MBAR + 8 * s;
            uint32_t dst = sbase + SM_TILES + s * STAGE_BYTES;
            mbar_expect_tx(mb, CHUNK_TX);
            BULK_G2S(dst,               aTiles + s * CHUNK_BYTES, CHUNK_BYTES, mb);
            BULK_G2S(dst + CHUNK_BYTES, bTiles + s * CHUNK_BYTES, CHUNK_BYTES, mb);
        }
    }
    __syncthreads();

    // f16x2 accumulators: acc[mi][ni][h] packs cols (e=0,e=1) for row-half h.
    uint32_t acc[4][4][2];
    #pragma unroll
    for (int mi = 0; mi < 4; ++mi)
        #pragma unroll
        for (int ni = 0; ni < 4; ++ni) { acc[mi][ni][0] = 0u; acc[mi][ni][1] = 0u; }

    // Fragment addressing: row r, 16B-unit col cu -> r*128 + ((cu ^ (r&7))<<4)
    const int lane15 = lane & 15;
    const int hi = lane >> 4;
    uint32_t aRow[4], aSw[4], bRow[2], bSw[2];
    #pragma unroll
    for (int mi = 0; mi < 4; ++mi) {
        int r = warpRow * 64 + mi * 16 + lane15;
        aRow[mi] = r << 7; aSw[mi] = r & 7;
    }
    #pragma unroll
    for (int nh = 0; nh < 2; ++nh) {
        int r = warpCol * 32 + nh * 16 + lane15;
        bRow[nh] = r << 7; bSw[nh] = r & 7;
    }

    #pragma unroll
    for (int c = 0; c < NCHUNK; ++c) {
        const int s = c % NSTAGE;
        const uint32_t mb = sbase + SM_MBAR + 8 * s;
        mbar_wait(mb, (c < NSTAGE) ? 0 : 1);

        const uint32_t abase = sbase + SM_TILES + s * STAGE_BYTES;
        const uint32_t bbase = abase + CHUNK_BYTES;

        #pragma unroll
        for (int ks = 0; ks < 4; ++ks) {
            const uint32_t cu = 2 * ks + hi;
            uint32_t ra[4][4], rb[2][4];
            #pragma unroll
            for (int mi = 0; mi < 4; ++mi)
                LDMATRIX_X4(ra[mi], abase + aRow[mi] + (((cu ^ aSw[mi])) << 4));
            #pragma unroll
            for (int nh = 0; nh < 2; ++nh)
                LDMATRIX_X4(rb[nh], bbase + bRow[nh] + (((cu ^ bSw[nh])) << 4));
            #pragma unroll
            for (int mi = 0; mi < 4; ++mi)
                #pragma unroll
                for (int ni = 0; ni < 4; ++ni) {
                    const int nh = ni >> 1, sel = ni & 1;
                    MMA_FP8_F16(acc[mi][ni], ra[mi], rb[nh][sel], rb[nh][2 + sel]);
                }
        }

        // After all warps consumed stage s (chunk c), refill it with chunk c+NSTAGE.
        if (c + NSTAGE < NCHUNK) {
            __syncthreads();
            if (tid == 0) {
                mbar_expect_tx(mb, CHUNK_TX);
                BULK_G2S(abase, aTiles + (c + NSTAGE) * CHUNK_BYTES, CHUNK_BYTES, mb);
                BULK_G2S(bbase, bTiles + (c + NSTAGE) * CHUNK_BYTES, CHUNK_BYTES, mb);
            }
        }
    }

    // Epilogue: exp(2*sim); row partials (mi,h) and col partials (ni,e).
    const int m0 = warpRow * 64, n0 = warpCol * 32;
    const int rowBase = i * TM, colBase = j * TM;
    float rowp[4][2], colp[4][2];
    #pragma unroll
    for (int a = 0; a < 4; ++a) { rowp[a][0] = rowp[a][1] = 0.f; colp[a][0] = colp[a][1] = 0.f; }

    #pragma unroll
    for (int mi = 0; mi < 4; ++mi)
        #pragma unroll
        for (int ni = 0; ni < 4; ++ni)
            #pragma unroll
            for (int h = 0; h < 2; ++h) {
                float2 f = __half22float2(*reinterpret_cast<const __half2*>(&acc[mi][ni][h]));
                #pragma unroll
                for (int e = 0; e < 2; ++e) {
                    float ex = __expf((e ? f.y : f.x) * INV_T);
                    if (diag) {
                        int lr = m0 + mi * 16 + (lane >> 2) + 8 * h;
                        int lc = n0 + ni * 8 + (lane & 3) * 2 + e;
                        if (lr == lc) ex = 0.f;
                    }
                    rowp[mi][h] += ex;
                    colp[ni][e] += ex;
                }
            }

    #pragma unroll
    for (int mi = 0; mi < 4; ++mi)
        #pragma unroll
        for (int h = 0; h < 2; ++h) {
            float v = rowp[mi][h];
            v += __shfl_xor_sync(0xffffffffu, v, 1);
            v += __shfl_xor_sync(0xffffffffu, v, 2);
            rowp[mi][h] = v;
        }
    if ((lane & 3) == 0) {
        #pragma unroll
        for (int mi = 0; mi < 4; ++mi)
            #pragma unroll
            for (int h = 0; h < 2; ++h)
                atomicAdd(&sumexp[rowBase + m0 + mi * 16 + (lane >> 2) + 8 * h], rowp[mi][h]);
    }

    if (!diag) {
        #pragma unroll
        for (int ni = 0; ni < 4; ++ni)
            #pragma unroll
            for (int e = 0; e < 2; ++e) {
                float v = colp[ni][e];
                v += __shfl_xor_sync(0xffffffffu, v, 4);
                v += __shfl_xor_sync(0xffffffffu, v, 8);
                v += __shfl_xor_sync(0xffffffffu, v, 16);
                colp[ni][e] = v;
            }
        if (lane < 4) {
            #pragma unroll
            for (int ni = 0; ni < 4; ++ni)
                #pragma unroll
                for (int e = 0; e < 2; ++e)
                    atomicAdd(&sumexp[colBase + n0 + ni * 8 + lane * 2 + e], colp[ni][e]);
        }
    }
}

// ---------------------------------------------------------------------------
// Kernel 4: loss partials -> atomicAdd into out (zeroed by pos_kernel).
// ---------------------------------------------------------------------------
__global__ void loss_kernel(const float* __restrict__ sumexp,
                            const float* __restrict__ pos,
                            float* __restrict__ out) {
    __shared__ float red[1024];
    int i = blockIdx.x * 1024 + threadIdx.x;
    red[threadIdx.x] = __logf(sumexp[i]) - pos[i];
    __syncthreads();
    for (int off = 512; off > 0; off >>= 1) {
        if (threadIdx.x < off) red[threadIdx.x] += red[threadIdx.x + off];
        __syncthreads();
    }
    if (threadIdx.x == 0) atomicAdd(out, red[0] * (1.0f / (float)TWO_N));
}

// ---------------------------------------------------------------------------
extern "C" void kernel_launch(void* const* d_in, const int* in_sizes, int n_in,
                              void* d_out, int out_size) {
    const float* z = (const float*)d_in[0];
    float* out = (float*)d_out;

    uint8_t* z8;   cudaGetSymbolAddress((void**)&z8, g_z8);
    float* sumexp; cudaGetSymbolAddress((void**)&sumexp, g_sumexp);
    float* pos;    cudaGetSymbolAddress((void**)&pos, g_pos);

    cudaFuncSetAttribute(tile_kernel, cudaFuncAttributeMaxDynamicSharedMemorySize, SMEM_BYTES);

    normalize_kernel<<<TWO_N, 128>>>(z, z8);
    pos_kernel<<<(TWO_N * 32) / 256, 256>>>(z, pos, sumexp, out);
    tile_kernel<<<NTILES, 256, SMEM_BYTES>>>(z8, sumexp);
    loss_kernel<<<TWO_N / 1024, 1024>>>(sumexp, pos, out);
}